// round 3
// baseline (speedup 1.0000x reference)
#include <cuda_runtime.h>
#include <cstdint>

#define T_STEPS 16384
#define HDIM 512
#define CLAMP_MAX_V 49688.0f

typedef unsigned long long u64;
typedef unsigned int u32;

// Scratch (device globals: allocation-free per harness rules)
__device__ float g_xg[(size_t)T_STEPS * 2048];   // x @ W_ih^T + b, [T][4H]
__device__ u64   g_hf[(size_t)T_STEPS * HDIM];   // packed {tag(hi32), h bits(lo32)} per (t,u)

// ---------------- helpers ----------------
__device__ __forceinline__ u64 ldcg64(const u64* p){
    u64 v;
    asm volatile("ld.global.cg.b64 %0, [%1];" : "=l"(v) : "l"(p));
    return v;
}
__device__ __forceinline__ void stcg64(u64* p, u64 v){
    asm volatile("st.global.cg.b64 [%0], %1;" :: "l"(p), "l"(v) : "memory");
}
__device__ __forceinline__ float fsig(float x){
    float e = __expf(-x);
    return __fdividef(1.0f, 1.0f + e);
}
__device__ __forceinline__ float ftanh(float x){
    // tanh(x) = sign(x) * (1 - 2/(exp(2|x|)+1)); overflow-safe
    float e = __expf(2.0f * fabsf(x));
    float r = 1.0f - __fdividef(2.0f, e + 1.0f);
    return copysignf(r, x);
}
__device__ __forceinline__ float dot4(float4 a, float4 b){
    return fmaf(a.x, b.x, fmaf(a.y, b.y, fmaf(a.z, b.z, a.w * b.w)));
}

// ---------------- kernel 0: clear tags (every replay) ----------------
__global__ void __launch_bounds__(256) clear_hf()
{
    // g_hf = 16384*512 u64 = 8,388,608 u64 = 4,194,304 uint4. 8192 blocks x 256 x 2.
    size_t idx = ((size_t)blockIdx.x * 256 + threadIdx.x) * 2;
    uint4* p = (uint4*)g_hf;
    uint4 z = make_uint4(0u, 0u, 0u, 0u);
    p[idx]     = z;
    p[idx + 1] = z;
}

// ---------------- kernel 1: x_gates GEMM ----------------
// C[T,2048] = x[T,512] @ W_ih^T[512,2048] + (b_ih+b_hh); 128x128 tiles, BK=16.
__global__ void __launch_bounds__(256) xgates_gemm(
    const float* __restrict__ X, const float* __restrict__ Wih,
    const float* __restrict__ bih, const float* __restrict__ bhh)
{
    __shared__ float As[16][128];
    __shared__ float Bs[16][128];
    const int bm = blockIdx.y * 128;
    const int bn = blockIdx.x * 128;
    const int tid = threadIdx.x;
    const int tx = tid & 15, ty = tid >> 4;

    float acc[8][8];
    #pragma unroll
    for (int i = 0; i < 8; i++)
        #pragma unroll
        for (int j = 0; j < 8; j++) acc[i][j] = 0.0f;

    for (int k0 = 0; k0 < 512; k0 += 16) {
        #pragma unroll
        for (int i = 0; i < 2; i++) {
            int f = tid + i * 256;
            int row = f >> 2;
            int kc = (f & 3) * 4;
            float4 a = *(const float4*)(X   + (size_t)(bm + row) * 512 + k0 + kc);
            As[kc+0][row] = a.x; As[kc+1][row] = a.y; As[kc+2][row] = a.z; As[kc+3][row] = a.w;
            float4 b = *(const float4*)(Wih + (size_t)(bn + row) * 512 + k0 + kc);
            Bs[kc+0][row] = b.x; Bs[kc+1][row] = b.y; Bs[kc+2][row] = b.z; Bs[kc+3][row] = b.w;
        }
        __syncthreads();
        #pragma unroll
        for (int kk = 0; kk < 16; kk++) {
            float a[8], b[8];
            *(float4*)&a[0] = *(const float4*)&As[kk][ty * 8];
            *(float4*)&a[4] = *(const float4*)&As[kk][ty * 8 + 4];
            *(float4*)&b[0] = *(const float4*)&Bs[kk][tx * 8];
            *(float4*)&b[4] = *(const float4*)&Bs[kk][tx * 8 + 4];
            #pragma unroll
            for (int i = 0; i < 8; i++)
                #pragma unroll
                for (int j = 0; j < 8; j++) acc[i][j] = fmaf(a[i], b[j], acc[i][j]);
        }
        __syncthreads();
    }

    float biasj[8];
    #pragma unroll
    for (int j = 0; j < 8; j++) {
        int n = bn + tx * 8 + j;
        biasj[j] = bih[n] + bhh[n];
    }
    #pragma unroll
    for (int i = 0; i < 8; i++) {
        int m = bm + ty * 8 + i;
        float* op = g_xg + (size_t)m * 2048 + bn + tx * 8;
        float4 v0 = make_float4(acc[i][0] + biasj[0], acc[i][1] + biasj[1],
                                acc[i][2] + biasj[2], acc[i][3] + biasj[3]);
        float4 v1 = make_float4(acc[i][4] + biasj[4], acc[i][5] + biasj[5],
                                acc[i][6] + biasj[6], acc[i][7] + biasj[7]);
        *(float4*)op       = v0;
        *(float4*)(op + 4) = v1;
    }
}

// ---------------- kernel 2: persistent LSTM scan ----------------
// 128 CTAs x 128 threads (all co-resident). CTA b owns hidden units [4b,4b+4).
// Warp w -> unit u. Each thread holds a 4x16-float W_hh slice in registers.
// Handoff: one st.global.cg.b64 per (t,u) packing {tag=1, h bits} — single-store
// atomic, data+flag cannot tear or reorder. Consumers poll the integer tag.
__global__ void __launch_bounds__(128) lstm_scan(const float* __restrict__ Whh)
{
    __shared__ float hsm[512];
    const int tid  = threadIdx.x;
    const int lane = tid & 31;
    const int warp = tid >> 5;
    const int u    = blockIdx.x * 4 + warp;   // hidden unit 0..511

    // resident weights: 4 gates x 4 float4 = 64 floats / thread
    float4 w[4][4];
    #pragma unroll
    for (int r = 0; r < 4; r++)
        #pragma unroll
        for (int k = 0; k < 4; k++)
            w[r][k] = *(const float4*)(Whh + (size_t)(r * 512 + u) * 512 + k * 128 + 4 * lane);

    float c = 0.0f;
    for (int t = 0; t < T_STEPS; ++t) {
        const float* xgt = g_xg + (size_t)t * 2048 + u;   // prefetch x-gates early
        float xgi = __ldg(xgt);
        float xgf = __ldg(xgt + 512);
        float xgg = __ldg(xgt + 1024);
        float xgo = __ldg(xgt + 1536);

        float a0 = 0.0f, a1 = 0.0f, a2 = 0.0f, a3 = 0.0f;
        if (t > 0) {
            // thread tid gathers units 4*tid .. 4*tid+3 of h_{t-1}
            const u64* hp = g_hf + (size_t)(t - 1) * 512 + 4 * tid;
            u64 v0 = ldcg64(hp + 0);
            u64 v1 = ldcg64(hp + 1);
            u64 v2 = ldcg64(hp + 2);
            u64 v3 = ldcg64(hp + 3);
            while (((v0 & v1 & v2 & v3) >> 32) != 1ull) {
                __nanosleep(32);
                if ((v0 >> 32) != 1ull) v0 = ldcg64(hp + 0);
                if ((v1 >> 32) != 1ull) v1 = ldcg64(hp + 1);
                if ((v2 >> 32) != 1ull) v2 = ldcg64(hp + 2);
                if ((v3 >> 32) != 1ull) v3 = ldcg64(hp + 3);
            }
            hsm[4 * tid + 0] = __uint_as_float((u32)v0);
            hsm[4 * tid + 1] = __uint_as_float((u32)v1);
            hsm[4 * tid + 2] = __uint_as_float((u32)v2);
            hsm[4 * tid + 3] = __uint_as_float((u32)v3);
            __syncthreads();

            float4 h0 = *(const float4*)&hsm[      4 * lane];
            float4 h1 = *(const float4*)&hsm[128 + 4 * lane];
            float4 h2 = *(const float4*)&hsm[256 + 4 * lane];
            float4 h3 = *(const float4*)&hsm[384 + 4 * lane];
            a0 = (dot4(w[0][0], h0) + dot4(w[0][1], h1)) + (dot4(w[0][2], h2) + dot4(w[0][3], h3));
            a1 = (dot4(w[1][0], h0) + dot4(w[1][1], h1)) + (dot4(w[1][2], h2) + dot4(w[1][3], h3));
            a2 = (dot4(w[2][0], h0) + dot4(w[2][1], h1)) + (dot4(w[2][2], h2) + dot4(w[2][3], h3));
            a3 = (dot4(w[3][0], h0) + dot4(w[3][1], h1)) + (dot4(w[3][2], h2) + dot4(w[3][3], h3));
            __syncthreads();   // protect hsm before next iteration's writes

            #pragma unroll
            for (int off = 16; off > 0; off >>= 1) {
                a0 += __shfl_xor_sync(0xffffffffu, a0, off);
                a1 += __shfl_xor_sync(0xffffffffu, a1, off);
                a2 += __shfl_xor_sync(0xffffffffu, a2, off);
                a3 += __shfl_xor_sync(0xffffffffu, a3, off);
            }
        }
        float gi = fsig (a0 + xgi);
        float gf = fsig (a1 + xgf);
        float gg = ftanh(a2 + xgg);
        float go = fsig (a3 + xgo);
        c = fmaf(gf, c, gi * gg);
        float h = go * ftanh(c);
        if (lane == 0)
            stcg64(g_hf + (size_t)t * 512 + u,
                   (1ull << 32) | (u64)__float_as_uint(h));
    }
}

// ---------------- kernel 3: fused FC + heads (static smem) ----------------
// Per CTA: 32 rows. inter[32,128] = hs @ fc_w^T + fc_b (in smem), then
// action = clip(inter @ fc1_w^T + fc1_b), obj = clip(inter @ fc2_w^T + fc2_b).
__global__ void __launch_bounds__(256) head_kernel(
    const float* __restrict__ fcw,  const float* __restrict__ fcb,
    const float* __restrict__ fc1w, const float* __restrict__ fc1b,
    const float* __restrict__ fc2w, const float* __restrict__ fc2b,
    float* __restrict__ out)
{
    __shared__ float a_s[32 * 32];       // [k][r]  hs tile (K-chunk 32)
    __shared__ float w_s[32 * 128];      // [k][c]  fc_w tile
    __shared__ float inter_s[32 * 132];  // [r][c]  padded

    const int tid = threadIdx.x;
    const int tx = tid & 31, ty = tid >> 5;
    const int r0 = blockIdx.x * 32;

    float acc[4][4];
    #pragma unroll
    for (int i = 0; i < 4; i++)
        #pragma unroll
        for (int j = 0; j < 4; j++) acc[i][j] = 0.0f;

    for (int k0 = 0; k0 < 512; k0 += 32) {
        {   // load hs tile transposed from packed g_hf: 32 rows x 32 k
            int r  = tid >> 3;           // 0..31
            int kq = tid & 7;            // 0..7 -> k offset kq*4
            const uint4* src = (const uint4*)(g_hf + (size_t)(r0 + r) * 512 + k0 + kq * 4);
            uint4 p0 = src[0];
            uint4 p1 = src[1];
            int k = kq * 4;
            a_s[(k+0)*32 + r] = __uint_as_float(p0.x);
            a_s[(k+1)*32 + r] = __uint_as_float(p0.z);
            a_s[(k+2)*32 + r] = __uint_as_float(p1.x);
            a_s[(k+3)*32 + r] = __uint_as_float(p1.z);
        }
        {   // load fc_w tile transposed: 128 cols x 32 k
            int cc = tid >> 1;           // 0..127
            int kh = tid & 1;            // 0..1 -> k range kh*16..+16
            const float* src = fcw + (size_t)cc * 512 + k0 + kh * 16;
            #pragma unroll
            for (int j = 0; j < 4; j++) {
                float4 v = *(const float4*)(src + 4 * j);
                int k = kh * 16 + 4 * j;
                w_s[(k+0)*128 + cc] = v.x; w_s[(k+1)*128 + cc] = v.y;
                w_s[(k+2)*128 + cc] = v.z; w_s[(k+3)*128 + cc] = v.w;
            }
        }
        __syncthreads();
        #pragma unroll 8
        for (int kk = 0; kk < 32; kk++) {
            float4 a4 = *(const float4*)&a_s[kk * 32  + ty * 4];
            float4 b4 = *(const float4*)&w_s[kk * 128 + tx * 4];
            acc[0][0] = fmaf(a4.x, b4.x, acc[0][0]); acc[0][1] = fmaf(a4.x, b4.y, acc[0][1]);
            acc[0][2] = fmaf(a4.x, b4.z, acc[0][2]); acc[0][3] = fmaf(a4.x, b4.w, acc[0][3]);
            acc[1][0] = fmaf(a4.y, b4.x, acc[1][0]); acc[1][1] = fmaf(a4.y, b4.y, acc[1][1]);
            acc[1][2] = fmaf(a4.y, b4.z, acc[1][2]); acc[1][3] = fmaf(a4.y, b4.w, acc[1][3]);
            acc[2][0] = fmaf(a4.z, b4.x, acc[2][0]); acc[2][1] = fmaf(a4.z, b4.y, acc[2][1]);
            acc[2][2] = fmaf(a4.z, b4.z, acc[2][2]); acc[2][3] = fmaf(a4.z, b4.w, acc[2][3]);
            acc[3][0] = fmaf(a4.w, b4.x, acc[3][0]); acc[3][1] = fmaf(a4.w, b4.y, acc[3][1]);
            acc[3][2] = fmaf(a4.w, b4.z, acc[3][2]); acc[3][3] = fmaf(a4.w, b4.w, acc[3][3]);
        }
        __syncthreads();
    }

    #pragma unroll
    for (int i = 0; i < 4; i++)
        #pragma unroll
        for (int j = 0; j < 4; j++)
            inter_s[(ty * 4 + i) * 132 + tx * 4 + j] = acc[i][j] + fcb[tx * 4 + j];
    __syncthreads();

    for (int idx = tid; idx < 32 * 53; idx += 256) {
        int row = idx / 53, cc = idx % 53;
        const float* w; float b;
        if (cc < 16) { w = fc1w + cc * 128;        b = fc1b[cc]; }
        else         { w = fc2w + (cc - 16) * 128; b = fc2b[cc - 16]; }
        float s = b;
        const float* ir = inter_s + row * 132;
        #pragma unroll
        for (int k = 0; k < 128; k += 4) {
            float4 wv = __ldg((const float4*)(w + k));
            s = fmaf(ir[k+0], wv.x, fmaf(ir[k+1], wv.y, fmaf(ir[k+2], wv.z, fmaf(ir[k+3], wv.w, s))));
        }
        s = fminf(fmaxf(s, 0.0f), CLAMP_MAX_V);
        int gr = r0 + row;
        if (cc < 16) out[(size_t)gr * 16 + cc] = s;
        else         out[(size_t)T_STEPS * 16 + (size_t)gr * 37 + (cc - 16)] = s;
    }
}

// ---------------- launch ----------------
extern "C" void kernel_launch(void* const* d_in, const int* in_sizes, int n_in,
                              void* d_out, int out_size)
{
    const float* x    = (const float*)d_in[0];
    const float* Wih  = (const float*)d_in[1];
    const float* Whh  = (const float*)d_in[2];
    const float* bih  = (const float*)d_in[3];
    const float* bhh  = (const float*)d_in[4];
    const float* fcw  = (const float*)d_in[5];
    const float* fcb  = (const float*)d_in[6];
    const float* fc1w = (const float*)d_in[7];
    const float* fc1b = (const float*)d_in[8];
    const float* fc2w = (const float*)d_in[9];
    const float* fc2b = (const float*)d_in[10];
    float* out = (float*)d_out;
    (void)in_sizes; (void)n_in; (void)out_size;

    clear_hf<<<8192, 256>>>();

    dim3 g1(2048 / 128, T_STEPS / 128);
    xgates_gemm<<<g1, 256>>>(x, Wih, bih, bhh);

    lstm_scan<<<128, 128>>>(Whh);

    head_kernel<<<T_STEPS / 32, 256>>>(fcw, fcb, fc1w, fc1b, fc2w, fc2b, out);
}

// round 8
// speedup vs baseline: 1.0084x; 1.0084x over previous
#include <cuda_runtime.h>
#include <cstdint>

#define T_STEPS 16384
#define HDIM 512
#define CLAMP_MAX_V 49688.0f

typedef unsigned long long u64;
typedef unsigned int u32;

// Scratch (device globals: allocation-free per harness rules).
// g_xg has one padding row so the t+1 prefetch is branchless at t = T-1.
__device__ float g_xg[(size_t)(T_STEPS + 1) * 2048];  // x @ W_ih^T + b, [T][4H]
__device__ u64   g_hf[(size_t)T_STEPS * HDIM];        // packed {tag(hi32), h bits(lo32)}

// ---------------- helpers ----------------
__device__ __forceinline__ u64 ldcg64(const u64* p){
    u64 v;
    asm volatile("ld.global.cg.b64 %0, [%1];" : "=l"(v) : "l"(p));
    return v;
}
__device__ __forceinline__ void stcg64(u64* p, u64 v){
    asm volatile("st.global.cg.b64 [%0], %1;" :: "l"(p), "l"(v) : "memory");
}
__device__ __forceinline__ float fsig(float x){
    float e = __expf(-x);
    return __fdividef(1.0f, 1.0f + e);
}
__device__ __forceinline__ float ftanh(float x){
    // tanh(x) = sign(x) * (1 - 2/(exp(2|x|)+1)); overflow-safe
    float e = __expf(2.0f * fabsf(x));
    float r = 1.0f - __fdividef(2.0f, e + 1.0f);
    return copysignf(r, x);
}
__device__ __forceinline__ float dot4(float4 a, float4 b){
    return fmaf(a.x, b.x, fmaf(a.y, b.y, fmaf(a.z, b.z, a.w * b.w)));
}

// ---------------- kernel 0: clear tags (every replay) ----------------
__global__ void __launch_bounds__(256) clear_hf()
{
    // g_hf = 16384*512 u64 = 4,194,304 uint4. 8192 blocks x 256 threads x 2.
    size_t idx = ((size_t)blockIdx.x * 256 + threadIdx.x) * 2;
    uint4* p = (uint4*)g_hf;
    uint4 z = make_uint4(0u, 0u, 0u, 0u);
    p[idx]     = z;
    p[idx + 1] = z;
}

// ---------------- kernel 1: x_gates GEMM ----------------
// C[T,2048] = x[T,512] @ W_ih^T[512,2048] + (b_ih+b_hh); 128x128 tiles, BK=16.
__global__ void __launch_bounds__(256) xgates_gemm(
    const float* __restrict__ X, const float* __restrict__ Wih,
    const float* __restrict__ bih, const float* __restrict__ bhh)
{
    __shared__ float As[16][128];
    __shared__ float Bs[16][128];
    const int bm = blockIdx.y * 128;
    const int bn = blockIdx.x * 128;
    const int tid = threadIdx.x;
    const int tx = tid & 15, ty = tid >> 4;

    float acc[8][8];
    #pragma unroll
    for (int i = 0; i < 8; i++)
        #pragma unroll
        for (int j = 0; j < 8; j++) acc[i][j] = 0.0f;

    for (int k0 = 0; k0 < 512; k0 += 16) {
        #pragma unroll
        for (int i = 0; i < 2; i++) {
            int f = tid + i * 256;
            int row = f >> 2;
            int kc = (f & 3) * 4;
            float4 a = *(const float4*)(X   + (size_t)(bm + row) * 512 + k0 + kc);
            As[kc+0][row] = a.x; As[kc+1][row] = a.y; As[kc+2][row] = a.z; As[kc+3][row] = a.w;
            float4 b = *(const float4*)(Wih + (size_t)(bn + row) * 512 + k0 + kc);
            Bs[kc+0][row] = b.x; Bs[kc+1][row] = b.y; Bs[kc+2][row] = b.z; Bs[kc+3][row] = b.w;
        }
        __syncthreads();
        #pragma unroll
        for (int kk = 0; kk < 16; kk++) {
            float a[8], b[8];
            *(float4*)&a[0] = *(const float4*)&As[kk][ty * 8];
            *(float4*)&a[4] = *(const float4*)&As[kk][ty * 8 + 4];
            *(float4*)&b[0] = *(const float4*)&Bs[kk][tx * 8];
            *(float4*)&b[4] = *(const float4*)&Bs[kk][tx * 8 + 4];
            #pragma unroll
            for (int i = 0; i < 8; i++)
                #pragma unroll
                for (int j = 0; j < 8; j++) acc[i][j] = fmaf(a[i], b[j], acc[i][j]);
        }
        __syncthreads();
    }

    float biasj[8];
    #pragma unroll
    for (int j = 0; j < 8; j++) {
        int n = bn + tx * 8 + j;
        biasj[j] = bih[n] + bhh[n];
    }
    #pragma unroll
    for (int i = 0; i < 8; i++) {
        int m = bm + ty * 8 + i;
        float* op = g_xg + (size_t)m * 2048 + bn + tx * 8;
        float4 v0 = make_float4(acc[i][0] + biasj[0], acc[i][1] + biasj[1],
                                acc[i][2] + biasj[2], acc[i][3] + biasj[3]);
        float4 v1 = make_float4(acc[i][4] + biasj[4], acc[i][5] + biasj[5],
                                acc[i][6] + biasj[6], acc[i][7] + biasj[7]);
        *(float4*)op       = v0;
        *(float4*)(op + 4) = v1;
    }
}

// ---------------- kernel 2: persistent LSTM scan ----------------
// 128 CTAs x 128 threads (all co-resident). CTA b owns hidden units [4b,4b+4).
// Warp w -> unit u. W_hh slice register-resident (64 floats/thread).
// Handoff: one st.global.cg.b64 per (t,u) packing {tag=1, h bits}; consumers
// tight-poll the integer tag (NO nanosleep). x_gates software-pipelined by 1.
__global__ void __launch_bounds__(128) lstm_scan(const float* __restrict__ Whh)
{
    __shared__ float hsm[2][512];
    const int tid  = threadIdx.x;
    const int lane = tid & 31;
    const int warp = tid >> 5;
    const int u    = blockIdx.x * 4 + warp;   // hidden unit 0..511

    // resident weights: 4 gates x 4 float4 = 64 floats / thread
    float4 w[4][4];
    #pragma unroll
    for (int r = 0; r < 4; r++)
        #pragma unroll
        for (int k = 0; k < 4; k++)
            w[r][k] = *(const float4*)(Whh + (size_t)(r * 512 + u) * 512 + k * 128 + 4 * lane);

    // prefetch x-gates for t=0
    float xgi = __ldg(g_xg + u);
    float xgf = __ldg(g_xg + u + 512);
    float xgg = __ldg(g_xg + u + 1024);
    float xgo = __ldg(g_xg + u + 1536);

    float c = 0.0f;
    for (int t = 0; t < T_STEPS; ++t) {
        // prefetch next step's x-gates (padding row makes this safe at t=T-1)
        const float* nx = g_xg + (size_t)(t + 1) * 2048 + u;
        float nxgi = __ldg(nx);
        float nxgf = __ldg(nx + 512);
        float nxgg = __ldg(nx + 1024);
        float nxgo = __ldg(nx + 1536);

        float a0 = 0.0f, a1 = 0.0f, a2 = 0.0f, a3 = 0.0f;
        if (t > 0) {
            // thread tid gathers units 4*tid .. 4*tid+3 of h_{t-1}; tight poll
            const u64* hp = g_hf + (size_t)(t - 1) * 512 + 4 * tid;
            u64 v0 = ldcg64(hp + 0);
            u64 v1 = ldcg64(hp + 1);
            u64 v2 = ldcg64(hp + 2);
            u64 v3 = ldcg64(hp + 3);
            while (((v0 & v1 & v2 & v3) >> 32) == 0ull) {
                if (!(v0 >> 32)) v0 = ldcg64(hp + 0);
                if (!(v1 >> 32)) v1 = ldcg64(hp + 1);
                if (!(v2 >> 32)) v2 = ldcg64(hp + 2);
                if (!(v3 >> 32)) v3 = ldcg64(hp + 3);
            }
            float* hb = hsm[t & 1];
            hb[4 * tid + 0] = __uint_as_float((u32)v0);
            hb[4 * tid + 1] = __uint_as_float((u32)v1);
            hb[4 * tid + 2] = __uint_as_float((u32)v2);
            hb[4 * tid + 3] = __uint_as_float((u32)v3);
            __syncthreads();   // only barrier per step (double-buffered hsm)

            float4 h0 = *(const float4*)&hb[      4 * lane];
            float4 h1 = *(const float4*)&hb[128 + 4 * lane];
            float4 h2 = *(const float4*)&hb[256 + 4 * lane];
            float4 h3 = *(const float4*)&hb[384 + 4 * lane];
            a0 = (dot4(w[0][0], h0) + dot4(w[0][1], h1)) + (dot4(w[0][2], h2) + dot4(w[0][3], h3));
            a1 = (dot4(w[1][0], h0) + dot4(w[1][1], h1)) + (dot4(w[1][2], h2) + dot4(w[1][3], h3));
            a2 = (dot4(w[2][0], h0) + dot4(w[2][1], h1)) + (dot4(w[2][2], h2) + dot4(w[2][3], h3));
            a3 = (dot4(w[3][0], h0) + dot4(w[3][1], h1)) + (dot4(w[3][2], h2) + dot4(w[3][3], h3));

            // warp-wide sum; 4 independent butterflies pipeline under each other
            #pragma unroll
            for (int off = 16; off > 0; off >>= 1) {
                a0 += __shfl_xor_sync(0xffffffffu, a0, off);
                a1 += __shfl_xor_sync(0xffffffffu, a1, off);
                a2 += __shfl_xor_sync(0xffffffffu, a2, off);
                a3 += __shfl_xor_sync(0xffffffffu, a3, off);
            }
        }
        float gi = fsig (a0 + xgi);
        float gf = fsig (a1 + xgf);
        float gg = ftanh(a2 + xgg);
        float go = fsig (a3 + xgo);
        c = fmaf(gf, c, gi * gg);
        float h = go * ftanh(c);
        if (lane == 0)
            stcg64(g_hf + (size_t)t * 512 + u,
                   (1ull << 32) | (u64)__float_as_uint(h));

        xgi = nxgi; xgf = nxgf; xgg = nxgg; xgo = nxgo;
    }
}

// ---------------- kernel 3: fused FC + heads (static smem) ----------------
__global__ void __launch_bounds__(256) head_kernel(
    const float* __restrict__ fcw,  const float* __restrict__ fcb,
    const float* __restrict__ fc1w, const float* __restrict__ fc1b,
    const float* __restrict__ fc2w, const float* __restrict__ fc2b,
    float* __restrict__ out)
{
    __shared__ float a_s[32 * 32];       // [k][r]  hs tile (K-chunk 32)
    __shared__ float w_s[32 * 128];      // [k][c]  fc_w tile
    __shared__ float inter_s[32 * 132];  // [r][c]  padded

    const int tid = threadIdx.x;
    const int tx = tid & 31, ty = tid >> 5;
    const int r0 = blockIdx.x * 32;

    float acc[4][4];
    #pragma unroll
    for (int i = 0; i < 4; i++)
        #pragma unroll
        for (int j = 0; j < 4; j++) acc[i][j] = 0.0f;

    for (int k0 = 0; k0 < 512; k0 += 32) {
        {   // load hs tile transposed from packed g_hf: 32 rows x 32 k
            int r  = tid >> 3;           // 0..31
            int kq = tid & 7;            // 0..7 -> k offset kq*4
            const uint4* src = (const uint4*)(g_hf + (size_t)(r0 + r) * 512 + k0 + kq * 4);
            uint4 p0 = src[0];
            uint4 p1 = src[1];
            int k = kq * 4;
            a_s[(k+0)*32 + r] = __uint_as_float(p0.x);
            a_s[(k+1)*32 + r] = __uint_as_float(p0.z);
            a_s[(k+2)*32 + r] = __uint_as_float(p1.x);
            a_s[(k+3)*32 + r] = __uint_as_float(p1.z);
        }
        {   // load fc_w tile transposed: 128 cols x 32 k
            int cc = tid >> 1;           // 0..127
            int kh = tid & 1;            // 0..1 -> k range kh*16..+16
            const float* src = fcw + (size_t)cc * 512 + k0 + kh * 16;
            #pragma unroll
            for (int j = 0; j < 4; j++) {
                float4 v = *(const float4*)(src + 4 * j);
                int k = kh * 16 + 4 * j;
                w_s[(k+0)*128 + cc] = v.x; w_s[(k+1)*128 + cc] = v.y;
                w_s[(k+2)*128 + cc] = v.z; w_s[(k+3)*128 + cc] = v.w;
            }
        }
        __syncthreads();
        #pragma unroll 8
        for (int kk = 0; kk < 32; kk++) {
            float4 a4 = *(const float4*)&a_s[kk * 32  + ty * 4];
            float4 b4 = *(const float4*)&w_s[kk * 128 + tx * 4];
            acc[0][0] = fmaf(a4.x, b4.x, acc[0][0]); acc[0][1] = fmaf(a4.x, b4.y, acc[0][1]);
            acc[0][2] = fmaf(a4.x, b4.z, acc[0][2]); acc[0][3] = fmaf(a4.x, b4.w, acc[0][3]);
            acc[1][0] = fmaf(a4.y, b4.x, acc[1][0]); acc[1][1] = fmaf(a4.y, b4.y, acc[1][1]);
            acc[1][2] = fmaf(a4.y, b4.z, acc[1][2]); acc[1][3] = fmaf(a4.y, b4.w, acc[1][3]);
            acc[2][0] = fmaf(a4.z, b4.x, acc[2][0]); acc[2][1] = fmaf(a4.z, b4.y, acc[2][1]);
            acc[2][2] = fmaf(a4.z, b4.z, acc[2][2]); acc[2][3] = fmaf(a4.z, b4.w, acc[2][3]);
            acc[3][0] = fmaf(a4.w, b4.x, acc[3][0]); acc[3][1] = fmaf(a4.w, b4.y, acc[3][1]);
            acc[3][2] = fmaf(a4.w, b4.z, acc[3][2]); acc[3][3] = fmaf(a4.w, b4.w, acc[3][3]);
        }
        __syncthreads();
    }

    #pragma unroll
    for (int i = 0; i < 4; i++)
        #pragma unroll
        for (int j = 0; j < 4; j++)
            inter_s[(ty * 4 + i) * 132 + tx * 4 + j] = acc[i][j] + fcb[tx * 4 + j];
    __syncthreads();

    for (int idx = tid; idx < 32 * 53; idx += 256) {
        int row = idx / 53, cc = idx % 53;
        const float* w; float b;
        if (cc < 16) { w = fc1w + cc * 128;        b = fc1b[cc]; }
        else         { w = fc2w + (cc - 16) * 128; b = fc2b[cc - 16]; }
        float s = b;
        const float* ir = inter_s + row * 132;
        #pragma unroll
        for (int k = 0; k < 128; k += 4) {
            float4 wv = __ldg((const float4*)(w + k));
            s = fmaf(ir[k+0], wv.x, fmaf(ir[k+1], wv.y, fmaf(ir[k+2], wv.z, fmaf(ir[k+3], wv.w, s))));
        }
        s = fminf(fmaxf(s, 0.0f), CLAMP_MAX_V);
        int gr = r0 + row;
        if (cc < 16) out[(size_t)gr * 16 + cc] = s;
        else         out[(size_t)T_STEPS * 16 + (size_t)gr * 37 + (cc - 16)] = s;
    }
}

// ---------------- launch ----------------
extern "C" void kernel_launch(void* const* d_in, const int* in_sizes, int n_in,
                              void* d_out, int out_size)
{
    const float* x    = (const float*)d_in[0];
    const float* Wih  = (const float*)d_in[1];
    const float* Whh  = (const float*)d_in[2];
    const float* bih  = (const float*)d_in[3];
    const float* bhh  = (const float*)d_in[4];
    const float* fcw  = (const float*)d_in[5];
    const float* fcb  = (const float*)d_in[6];
    const float* fc1w = (const float*)d_in[7];
    const float* fc1b = (const float*)d_in[8];
    const float* fc2w = (const float*)d_in[9];
    const float* fc2b = (const float*)d_in[10];
    float* out = (float*)d_out;
    (void)in_sizes; (void)n_in; (void)out_size;

    clear_hf<<<8192, 256>>>();

    dim3 g1(2048 / 128, T_STEPS / 128);
    xgates_gemm<<<g1, 256>>>(x, Wih, bih, bhh);

    lstm_scan<<<128, 128>>>(Whh);

    head_kernel<<<T_STEPS / 32, 256>>>(fcw, fcb, fc1w, fc1b, fc2w, fc2b, out);
}

// round 10
// speedup vs baseline: 1.0093x; 1.0009x over previous
#include <cuda_runtime.h>
#include <cstdint>

#define T_STEPS 16384
#define HDIM 512
#define CLAMP_MAX_V 49688.0f

typedef unsigned long long u64;
typedef unsigned int u32;

// Scratch (device globals: allocation-free per harness rules).
// g_xg has one padding row so the t+1 prefetch is branchless at t = T-1.
__device__ float g_xg[(size_t)(T_STEPS + 1) * 2048];  // x @ W_ih^T + b, [T][4H]
__device__ u64   g_hf[(size_t)T_STEPS * HDIM];        // packed {tag(hi32), h bits(lo32)}

// ---------------- helpers ----------------
__device__ __forceinline__ u64 ldcg64(const u64* p){
    u64 v;
    asm volatile("ld.global.cg.b64 %0, [%1];" : "=l"(v) : "l"(p));
    return v;
}
__device__ __forceinline__ void stcg64(u64* p, u64 v){
    asm volatile("st.global.cg.b64 [%0], %1;" :: "l"(p), "l"(v) : "memory");
}
__device__ __forceinline__ float fsig(float x){
    float e = __expf(-x);
    return __fdividef(1.0f, 1.0f + e);
}
__device__ __forceinline__ float ftanh(float x){
    // tanh(x) = sign(x) * (1 - 2/(exp(2|x|)+1)); overflow-safe
    float e = __expf(2.0f * fabsf(x));
    float r = 1.0f - __fdividef(2.0f, e + 1.0f);
    return copysignf(r, x);
}
__device__ __forceinline__ float dot4(float4 a, float4 b){
    return fmaf(a.x, b.x, fmaf(a.y, b.y, fmaf(a.z, b.z, a.w * b.w)));
}

// ---------------- kernel 0: clear tags (every replay) ----------------
__global__ void __launch_bounds__(256) clear_hf()
{
    // g_hf = 16384*512 u64 = 4,194,304 uint4. 8192 blocks x 256 threads x 2.
    size_t idx = ((size_t)blockIdx.x * 256 + threadIdx.x) * 2;
    uint4* p = (uint4*)g_hf;
    uint4 z = make_uint4(0u, 0u, 0u, 0u);
    p[idx]     = z;
    p[idx + 1] = z;
}

// ---------------- kernel 1: x_gates GEMM ----------------
// C[T,2048] = x[T,512] @ W_ih^T[512,2048] + (b_ih+b_hh); 128x128 tiles, BK=16.
__global__ void __launch_bounds__(256) xgates_gemm(
    const float* __restrict__ X, const float* __restrict__ Wih,
    const float* __restrict__ bih, const float* __restrict__ bhh)
{
    __shared__ float As[16][128];
    __shared__ float Bs[16][128];
    const int bm = blockIdx.y * 128;
    const int bn = blockIdx.x * 128;
    const int tid = threadIdx.x;
    const int tx = tid & 15, ty = tid >> 4;

    float acc[8][8];
    #pragma unroll
    for (int i = 0; i < 8; i++)
        #pragma unroll
        for (int j = 0; j < 8; j++) acc[i][j] = 0.0f;

    for (int k0 = 0; k0 < 512; k0 += 16) {
        #pragma unroll
        for (int i = 0; i < 2; i++) {
            int f = tid + i * 256;
            int row = f >> 2;
            int kc = (f & 3) * 4;
            float4 a = *(const float4*)(X   + (size_t)(bm + row) * 512 + k0 + kc);
            As[kc+0][row] = a.x; As[kc+1][row] = a.y; As[kc+2][row] = a.z; As[kc+3][row] = a.w;
            float4 b = *(const float4*)(Wih + (size_t)(bn + row) * 512 + k0 + kc);
            Bs[kc+0][row] = b.x; Bs[kc+1][row] = b.y; Bs[kc+2][row] = b.z; Bs[kc+3][row] = b.w;
        }
        __syncthreads();
        #pragma unroll
        for (int kk = 0; kk < 16; kk++) {
            float a[8], b[8];
            *(float4*)&a[0] = *(const float4*)&As[kk][ty * 8];
            *(float4*)&a[4] = *(const float4*)&As[kk][ty * 8 + 4];
            *(float4*)&b[0] = *(const float4*)&Bs[kk][tx * 8];
            *(float4*)&b[4] = *(const float4*)&Bs[kk][tx * 8 + 4];
            #pragma unroll
            for (int i = 0; i < 8; i++)
                #pragma unroll
                for (int j = 0; j < 8; j++) acc[i][j] = fmaf(a[i], b[j], acc[i][j]);
        }
        __syncthreads();
    }

    float biasj[8];
    #pragma unroll
    for (int j = 0; j < 8; j++) {
        int n = bn + tx * 8 + j;
        biasj[j] = bih[n] + bhh[n];
    }
    #pragma unroll
    for (int i = 0; i < 8; i++) {
        int m = bm + ty * 8 + i;
        float* op = g_xg + (size_t)m * 2048 + bn + tx * 8;
        float4 v0 = make_float4(acc[i][0] + biasj[0], acc[i][1] + biasj[1],
                                acc[i][2] + biasj[2], acc[i][3] + biasj[3]);
        float4 v1 = make_float4(acc[i][4] + biasj[4], acc[i][5] + biasj[5],
                                acc[i][6] + biasj[6], acc[i][7] + biasj[7]);
        *(float4*)op       = v0;
        *(float4*)(op + 4) = v1;
    }
}

// ---------------- kernel 2: persistent LSTM scan ----------------
// 128 CTAs x 128 threads (all co-resident). CTA b owns hidden units [4b,4b+4).
// Warp w -> unit u. W_hh slice register-resident (64 floats/thread).
// Handoff: one st.global.cg.b64 per (t,u) packing {tag=1, h bits}; consumers
// tight-poll the integer tag (NO nanosleep). x_gates software-pipelined by 1.
__global__ void __launch_bounds__(128) lstm_scan(const float* __restrict__ Whh)
{
    __shared__ float hsm[2][512];
    const int tid  = threadIdx.x;
    const int lane = tid & 31;
    const int warp = tid >> 5;
    const int u    = blockIdx.x * 4 + warp;   // hidden unit 0..511

    // resident weights: 4 gates x 4 float4 = 64 floats / thread
    float4 w[4][4];
    #pragma unroll
    for (int r = 0; r < 4; r++)
        #pragma unroll
        for (int k = 0; k < 4; k++)
            w[r][k] = *(const float4*)(Whh + (size_t)(r * 512 + u) * 512 + k * 128 + 4 * lane);

    // prefetch x-gates for t=0
    float xgi = __ldg(g_xg + u);
    float xgf = __ldg(g_xg + u + 512);
    float xgg = __ldg(g_xg + u + 1024);
    float xgo = __ldg(g_xg + u + 1536);

    float c = 0.0f;
    for (int t = 0; t < T_STEPS; ++t) {
        // prefetch next step's x-gates (padding row makes this safe at t=T-1)
        const float* nx = g_xg + (size_t)(t + 1) * 2048 + u;
        float nxgi = __ldg(nx);
        float nxgf = __ldg(nx + 512);
        float nxgg = __ldg(nx + 1024);
        float nxgo = __ldg(nx + 1536);

        float a0 = 0.0f, a1 = 0.0f, a2 = 0.0f, a3 = 0.0f;
        if (t > 0) {
            // thread tid gathers units 4*tid .. 4*tid+3 of h_{t-1}; tight poll
            const u64* hp = g_hf + (size_t)(t - 1) * 512 + 4 * tid;
            u64 v0 = ldcg64(hp + 0);
            u64 v1 = ldcg64(hp + 1);
            u64 v2 = ldcg64(hp + 2);
            u64 v3 = ldcg64(hp + 3);
            while (((v0 & v1 & v2 & v3) >> 32) == 0ull) {
                if (!(v0 >> 32)) v0 = ldcg64(hp + 0);
                if (!(v1 >> 32)) v1 = ldcg64(hp + 1);
                if (!(v2 >> 32)) v2 = ldcg64(hp + 2);
                if (!(v3 >> 32)) v3 = ldcg64(hp + 3);
            }
            float* hb = hsm[t & 1];
            hb[4 * tid + 0] = __uint_as_float((u32)v0);
            hb[4 * tid + 1] = __uint_as_float((u32)v1);
            hb[4 * tid + 2] = __uint_as_float((u32)v2);
            hb[4 * tid + 3] = __uint_as_float((u32)v3);
            __syncthreads();   // only barrier per step (double-buffered hsm)

            float4 h0 = *(const float4*)&hb[      4 * lane];
            float4 h1 = *(const float4*)&hb[128 + 4 * lane];
            float4 h2 = *(const float4*)&hb[256 + 4 * lane];
            float4 h3 = *(const float4*)&hb[384 + 4 * lane];
            a0 = (dot4(w[0][0], h0) + dot4(w[0][1], h1)) + (dot4(w[0][2], h2) + dot4(w[0][3], h3));
            a1 = (dot4(w[1][0], h0) + dot4(w[1][1], h1)) + (dot4(w[1][2], h2) + dot4(w[1][3], h3));
            a2 = (dot4(w[2][0], h0) + dot4(w[2][1], h1)) + (dot4(w[2][2], h2) + dot4(w[2][3], h3));
            a3 = (dot4(w[3][0], h0) + dot4(w[3][1], h1)) + (dot4(w[3][2], h2) + dot4(w[3][3], h3));

            // warp-wide sum; 4 independent butterflies pipeline under each other
            #pragma unroll
            for (int off = 16; off > 0; off >>= 1) {
                a0 += __shfl_xor_sync(0xffffffffu, a0, off);
                a1 += __shfl_xor_sync(0xffffffffu, a1, off);
                a2 += __shfl_xor_sync(0xffffffffu, a2, off);
                a3 += __shfl_xor_sync(0xffffffffu, a3, off);
            }
        }
        float gi = fsig (a0 + xgi);
        float gf = fsig (a1 + xgf);
        float gg = ftanh(a2 + xgg);
        float go = fsig (a3 + xgo);
        c = fmaf(gf, c, gi * gg);
        float h = go * ftanh(c);
        if (lane == 0)
            stcg64(g_hf + (size_t)t * 512 + u,
                   (1ull << 32) | (u64)__float_as_uint(h));

        xgi = nxgi; xgf = nxgf; xgg = nxgg; xgo = nxgo;
    }
}

// ---------------- kernel 3: fused FC + heads (static smem) ----------------
__global__ void __launch_bounds__(256) head_kernel(
    const float* __restrict__ fcw,  const float* __restrict__ fcb,
    const float* __restrict__ fc1w, const float* __restrict__ fc1b,
    const float* __restrict__ fc2w, const float* __restrict__ fc2b,
    float* __restrict__ out)
{
    __shared__ float a_s[32 * 32];       // [k][r]  hs tile (K-chunk 32)
    __shared__ float w_s[32 * 128];      // [k][c]  fc_w tile
    __shared__ float inter_s[32 * 132];  // [r][c]  padded

    const int tid = threadIdx.x;
    const int tx = tid & 31, ty = tid >> 5;
    const int r0 = blockIdx.x * 32;

    float acc[4][4];
    #pragma unroll
    for (int i = 0; i < 4; i++)
        #pragma unroll
        for (int j = 0; j < 4; j++) acc[i][j] = 0.0f;

    for (int k0 = 0; k0 < 512; k0 += 32) {
        {   // load hs tile transposed from packed g_hf: 32 rows x 32 k
            int r  = tid >> 3;           // 0..31
            int kq = tid & 7;            // 0..7 -> k offset kq*4
            const uint4* src = (const uint4*)(g_hf + (size_t)(r0 + r) * 512 + k0 + kq * 4);
            uint4 p0 = src[0];
            uint4 p1 = src[1];
            int k = kq * 4;
            a_s[(k+0)*32 + r] = __uint_as_float(p0.x);
            a_s[(k+1)*32 + r] = __uint_as_float(p0.z);
            a_s[(k+2)*32 + r] = __uint_as_float(p1.x);
            a_s[(k+3)*32 + r] = __uint_as_float(p1.z);
        }
        {   // load fc_w tile transposed: 128 cols x 32 k
            int cc = tid >> 1;           // 0..127
            int kh = tid & 1;            // 0..1 -> k range kh*16..+16
            const float* src = fcw + (size_t)cc * 512 + k0 + kh * 16;
            #pragma unroll
            for (int j = 0; j < 4; j++) {
                float4 v = *(const float4*)(src + 4 * j);
                int k = kh * 16 + 4 * j;
                w_s[(k+0)*128 + cc] = v.x; w_s[(k+1)*128 + cc] = v.y;
                w_s[(k+2)*128 + cc] = v.z; w_s[(k+3)*128 + cc] = v.w;
            }
        }
        __syncthreads();
        #pragma unroll 8
        for (int kk = 0; kk < 32; kk++) {
            float4 a4 = *(const float4*)&a_s[kk * 32  + ty * 4];
            float4 b4 = *(const float4*)&w_s[kk * 128 + tx * 4];
            acc[0][0] = fmaf(a4.x, b4.x, acc[0][0]); acc[0][1] = fmaf(a4.x, b4.y, acc[0][1]);
            acc[0][2] = fmaf(a4.x, b4.z, acc[0][2]); acc[0][3] = fmaf(a4.x, b4.w, acc[0][3]);
            acc[1][0] = fmaf(a4.y, b4.x, acc[1][0]); acc[1][1] = fmaf(a4.y, b4.y, acc[1][1]);
            acc[1][2] = fmaf(a4.y, b4.z, acc[1][2]); acc[1][3] = fmaf(a4.y, b4.w, acc[1][3]);
            acc[2][0] = fmaf(a4.z, b4.x, acc[2][0]); acc[2][1] = fmaf(a4.z, b4.y, acc[2][1]);
            acc[2][2] = fmaf(a4.z, b4.z, acc[2][2]); acc[2][3] = fmaf(a4.z, b4.w, acc[2][3]);
            acc[3][0] = fmaf(a4.w, b4.x, acc[3][0]); acc[3][1] = fmaf(a4.w, b4.y, acc[3][1]);
            acc[3][2] = fmaf(a4.w, b4.z, acc[3][2]); acc[3][3] = fmaf(a4.w, b4.w, acc[3][3]);
        }
        __syncthreads();
    }

    #pragma unroll
    for (int i = 0; i < 4; i++)
        #pragma unroll
        for (int j = 0; j < 4; j++)
            inter_s[(ty * 4 + i) * 132 + tx * 4 + j] = acc[i][j] + fcb[tx * 4 + j];
    __syncthreads();

    for (int idx = tid; idx < 32 * 53; idx += 256) {
        int row = idx / 53, cc = idx % 53;
        const float* w; float b;
        if (cc < 16) { w = fc1w + cc * 128;        b = fc1b[cc]; }
        else         { w = fc2w + (cc - 16) * 128; b = fc2b[cc - 16]; }
        float s = b;
        const float* ir = inter_s + row * 132;
        #pragma unroll
        for (int k = 0; k < 128; k += 4) {
            float4 wv = __ldg((const float4*)(w + k));
            s = fmaf(ir[k+0], wv.x, fmaf(ir[k+1], wv.y, fmaf(ir[k+2], wv.z, fmaf(ir[k+3], wv.w, s))));
        }
        s = fminf(fmaxf(s, 0.0f), CLAMP_MAX_V);
        int gr = r0 + row;
        if (cc < 16) out[(size_t)gr * 16 + cc] = s;
        else         out[(size_t)T_STEPS * 16 + (size_t)gr * 37 + (cc - 16)] = s;
    }
}

// ---------------- launch ----------------
extern "C" void kernel_launch(void* const* d_in, const int* in_sizes, int n_in,
                              void* d_out, int out_size)
{
    const float* x    = (const float*)d_in[0];
    const float* Wih  = (const float*)d_in[1];
    const float* Whh  = (const float*)d_in[2];
    const float* bih  = (const float*)d_in[3];
    const float* bhh  = (const float*)d_in[4];
    const float* fcw  = (const float*)d_in[5];
    const float* fcb  = (const float*)d_in[6];
    const float* fc1w = (const float*)d_in[7];
    const float* fc1b = (const float*)d_in[8];
    const float* fc2w = (const float*)d_in[9];
    const float* fc2b = (const float*)d_in[10];
    float* out = (float*)d_out;
    (void)in_sizes; (void)n_in; (void)out_size;

    clear_hf<<<8192, 256>>>();

    dim3 g1(2048 / 128, T_STEPS / 128);
    xgates_gemm<<<g1, 256>>>(x, Wih, bih, bhh);

    lstm_scan<<<128, 128>>>(Whh);

    head_kernel<<<T_STEPS / 32, 256>>>(fcw, fcb, fc1w, fc1b, fc2w, fc2b, out);
}